// round 1
// baseline (speedup 1.0000x reference)
#include <cuda_runtime.h>
#include <cuda_fp16.h>
#include <cstdint>
#include <math.h>

// Problem constants
#define SEQ   512
#define BATCH 64
#define HID   1024
#define NG    4096            // 4*HID
#define MROWS (SEQ*BATCH)     // 32768

// ---------------- static device scratch (no allocs allowed) ----------------
__device__ float  d_gx [(size_t)SEQ*BATCH*NG];   // 512 MB, fp32 gate preacts
__device__ __half d_xh [(size_t)SEQ*BATCH*HID];  // x transposed to [s][b][h] fp16
__device__ __half d_hs0[(size_t)SEQ*BATCH*HID];  // layer-0 hidden sequence
__device__ __half d_hs1[(size_t)SEQ*BATCH*HID];  // layer-1 hidden sequence
__device__ __half d_wti[(size_t)2*NG*HID];       // Wi transposed: [l][n=g*H+h][d] fp16
__device__ __half d_wth[(size_t)2*NG*HID];       // Wh transposed: [l][n][d] fp16
__device__ float  d_biasT[2*NG];                 // bi + bh folded
__device__ unsigned d_barcnt;
__device__ unsigned d_bargen;

// ---------------- small PTX helpers ----------------
__device__ __forceinline__ void cpa16(void* s, const void* g){
    uint32_t sa = (uint32_t)__cvta_generic_to_shared(s);
    asm volatile("cp.async.cg.shared.global [%0],[%1],16;\n" :: "r"(sa), "l"(g));
}
#define CPCOMMIT() asm volatile("cp.async.commit_group;\n")
template<int N> __device__ __forceinline__ void cpwait(){
    asm volatile("cp.async.wait_group %0;\n" :: "n"(N));
}
__device__ __forceinline__ void mma16816(float* c, const uint32_t* a, const uint32_t* b){
    asm volatile(
        "mma.sync.aligned.m16n8k16.row.col.f32.f16.f16.f32 "
        "{%0,%1,%2,%3},{%4,%5,%6,%7},{%8,%9},{%0,%1,%2,%3};\n"
        : "+f"(c[0]), "+f"(c[1]), "+f"(c[2]), "+f"(c[3])
        : "r"(a[0]), "r"(a[1]), "r"(a[2]), "r"(a[3]), "r"(b[0]), "r"(b[1]));
}

// ---------------- converts ----------------
// x [B][S][H] f32  ->  xh [S][B][H] fp16
__global__ void k_convx(const float* __restrict__ x){
    size_t i = (size_t)blockIdx.x*256 + threadIdx.x;      // 33,554,432 total
    int h = (int)(i & 1023);
    size_t t = i >> 10;
    int s = (int)(t & 511);
    int b = (int)(t >> 9);
    d_xh[((size_t)s*BATCH + b)*HID + h] = __float2half(x[i]);
}

// Wi/Wh [l][g][d][h] f32 -> Wt [l][g*H+h][d] fp16 (transpose d<->h, tiled)
__global__ void k_convw(const float* __restrict__ Wi, const float* __restrict__ Wh){
    __shared__ float sm[32][33];
    int z   = blockIdx.z;
    int sel = z >> 3;          // 0 = Wi, 1 = Wh
    int l   = (z >> 2) & 1;
    int g   = z & 3;
    const float* src = (sel ? Wh : Wi) + ((size_t)(l*4 + g)) * 1024u * 1024u;
    __half* dst = (sel ? d_wth : d_wti) + ((size_t)l*NG + (size_t)g*1024) * 1024u;
    int d0 = blockIdx.x*32, h0 = blockIdx.y*32;
    sm[threadIdx.y][threadIdx.x] = src[(size_t)(d0+threadIdx.y)*1024 + (h0+threadIdx.x)];
    __syncthreads();
    dst[(size_t)(h0+threadIdx.y)*1024 + (d0+threadIdx.x)] = __float2half(sm[threadIdx.x][threadIdx.y]);
}

__global__ void k_bias(const float* __restrict__ bi, const float* __restrict__ bh){
    int i = blockIdx.x*256 + threadIdx.x;   // 8192
    d_biasT[i] = bi[i] + bh[i];
}

// ---------------- big input-projection GEMM ----------------
// C[MROWS][NG] = A[MROWS][1024] * W[n][k]^T + biasT   (A rows are (s,b))
__global__ void __launch_bounds__(256) k_gemm(int layer){
    const __half* __restrict__ Aptr = layer ? d_hs0 : d_xh;
    const __half* __restrict__ Wptr = d_wti + (size_t)layer*NG*HID;
    const float*  __restrict__ bias = d_biasT + layer*NG;
    float* __restrict__ Cout = d_gx;

    __shared__ __half As[2][128][40];
    __shared__ __half Bs[2][128][40];

    int tid = threadIdx.x, lane = tid & 31, w = tid >> 5;
    int grp = lane >> 2, tig = lane & 3;
    int wm = w & 1, wn = w >> 1;                 // 2 m-warps x 4 n-warps
    size_t m0 = (size_t)blockIdx.y*128, n0 = (size_t)blockIdx.x*128;

    float acc[4][4][4];
#pragma unroll
    for (int a=0;a<4;a++)
#pragma unroll
        for (int b=0;b<4;b++)
#pragma unroll
            for (int c=0;c<4;c++) acc[a][b][c] = 0.f;

#define GEMM_STAGE(BUF,KC) do{                                                   \
    _Pragma("unroll")                                                            \
    for (int rr=0; rr<2; rr++){                                                  \
        int idx = tid + rr*256; int row = idx>>2, seg = idx&3;                   \
        cpa16(&As[BUF][row][seg*8], Aptr + (m0+row)*HID + (KC)*32 + seg*8);      \
        cpa16(&Bs[BUF][row][seg*8], Wptr + (n0+row)*HID + (KC)*32 + seg*8);      \
    } }while(0)

    GEMM_STAGE(0,0); CPCOMMIT();
    for (int kc=0; kc<32; kc++){
        if (kc+1 < 32){ GEMM_STAGE((kc+1)&1, kc+1); CPCOMMIT(); cpwait<1>(); }
        else          { cpwait<0>(); }
        __syncthreads();
        int buf = kc & 1;
#pragma unroll
        for (int kk=0; kk<2; kk++){
            uint32_t ar[4][4], br[4][2];
            int k0 = kk*16 + tig*2;
#pragma unroll
            for (int mi=0; mi<4; mi++){
                int r = wm*64 + mi*16 + grp;
                ar[mi][0] = *(const uint32_t*)&As[buf][r  ][k0  ];
                ar[mi][1] = *(const uint32_t*)&As[buf][r+8][k0  ];
                ar[mi][2] = *(const uint32_t*)&As[buf][r  ][k0+8];
                ar[mi][3] = *(const uint32_t*)&As[buf][r+8][k0+8];
            }
#pragma unroll
            for (int ni=0; ni<4; ni++){
                int n = wn*32 + ni*8 + grp;
                br[ni][0] = *(const uint32_t*)&Bs[buf][n][k0  ];
                br[ni][1] = *(const uint32_t*)&Bs[buf][n][k0+8];
            }
#pragma unroll
            for (int mi=0; mi<4; mi++)
#pragma unroll
                for (int ni=0; ni<4; ni++)
                    mma16816(acc[mi][ni], ar[mi], br[ni]);
        }
        __syncthreads();
    }
#undef GEMM_STAGE

#pragma unroll
    for (int mi=0; mi<4; mi++){
        size_t r = m0 + wm*64 + mi*16 + grp;
#pragma unroll
        for (int ni=0; ni<4; ni++){
            size_t n = n0 + wn*32 + ni*8 + tig*2;
            float b0 = bias[n], b1 = bias[n+1];
            Cout[ r   *NG + n  ] = acc[mi][ni][0] + b0;
            Cout[ r   *NG + n+1] = acc[mi][ni][1] + b1;
            Cout[(r+8)*NG + n  ] = acc[mi][ni][2] + b0;
            Cout[(r+8)*NG + n+1] = acc[mi][ni][3] + b1;
        }
    }
}

// ---------------- persistent recurrent scan ----------------
__device__ __forceinline__ void grid_bar(){
    __syncthreads();
    if (threadIdx.x == 0){
        __threadfence();
        unsigned g = *(volatile unsigned*)&d_bargen;
        unsigned t = atomicAdd(&d_barcnt, 1u);
        if (t == gridDim.x - 1){
            d_barcnt = 0;
            __threadfence();
            atomicExch(&d_bargen, g + 1u);
        } else {
            while (*(volatile unsigned*)&d_bargen == g) { __nanosleep(40); }
        }
        __threadfence();
    }
    __syncthreads();
}

// 128 CTAs x 256 threads. CTA owns hcols [cta*8, cta*8+8) across all 4 gates.
// Wh slice (32 n-rows x 1024 k) resident in SMEM for all 512 steps.
__global__ void __launch_bounds__(256) k_scan(int layer, float* __restrict__ out){
    extern __shared__ char smem[];
    __half* Whs = (__half*)smem;                                  // [32][1032]
    __half* Ash = (__half*)(smem + 32*1032*2);                    // [2][64][40]
    float*  Cs  = (float*)(smem + 32*1032*2 + 2*64*40*2);         // [64][32]
#define WHS(j,k)   Whs[(j)*1032 + (k)]
#define ASB(b,r,k) Ash[(((b)*64)+(r))*40 + (k)]
#define CSE(r,c)   Cs[(r)*32 + (c)]

    const float*  __restrict__ gx  = d_gx;
    const __half* __restrict__ Whl = d_wth + (size_t)layer*NG*HID;
    __half* __restrict__ hsb = layer ? d_hs1 : d_hs0;

    int tid = threadIdx.x, lane = tid & 31, w = tid >> 5;
    int grp = lane >> 2, tig = lane & 3;
    int mrow0 = (w & 3)*16;            // 4 m-warps of 16 rows
    int ncol0 = (w >> 2)*16;           // 2 n-warps of 16 cols
    int hcol0 = blockIdx.x * 8;

    // Load resident Wh slice: row j -> n = (j>>3)*1024 + hcol0 + (j&7)
    for (int idx = tid; idx < 32*128; idx += 256){
        int j = idx >> 7, seg = idx & 127;
        int gate = j >> 3, hc = hcol0 + (j & 7);
        const __half* srcr = Whl + ((size_t)gate*1024 + hc)*1024;
        *(float4*)&WHS(j, seg*8) = *(const float4*)&srcr[seg*8];
    }
    __syncthreads();

    float creg0 = 0.f, creg1 = 0.f;

    for (int s = 0; s < SEQ; s++){
        if (s > 0){
            float acc[2][4];
#pragma unroll
            for (int ni=0; ni<2; ni++)
#pragma unroll
                for (int c=0; c<4; c++) acc[ni][c] = 0.f;

            const __half* hprev = hsb + (size_t)(s-1)*BATCH*HID;
            { int row = tid>>2, seg = tid&3;
              cpa16(&ASB(0,row,seg*8), hprev + (size_t)row*HID + seg*8); }
            CPCOMMIT();
            for (int kc=0; kc<32; kc++){
                if (kc+1 < 32){
                    int nb = (kc+1)&1; int row = tid>>2, seg = tid&3;
                    cpa16(&ASB(nb,row,seg*8), hprev + (size_t)row*HID + (kc+1)*32 + seg*8);
                    CPCOMMIT(); cpwait<1>();
                } else cpwait<0>();
                __syncthreads();
                int buf = kc & 1;
#pragma unroll
                for (int kk=0; kk<2; kk++){
                    uint32_t ar[4], br[2];
                    int k0 = kk*16 + tig*2;
                    int r  = mrow0 + grp;
                    ar[0] = *(const uint32_t*)&ASB(buf, r,   k0  );
                    ar[1] = *(const uint32_t*)&ASB(buf, r+8, k0  );
                    ar[2] = *(const uint32_t*)&ASB(buf, r,   k0+8);
                    ar[3] = *(const uint32_t*)&ASB(buf, r+8, k0+8);
                    int kg = kc*32 + kk*16 + tig*2;
#pragma unroll
                    for (int ni=0; ni<2; ni++){
                        int j = ncol0 + ni*8 + grp;
                        br[0] = *(const uint32_t*)&WHS(j, kg  );
                        br[1] = *(const uint32_t*)&WHS(j, kg+8);
                        mma16816(acc[ni], ar, br);
                    }
                }
                __syncthreads();
            }
            { int r = mrow0 + grp;
#pragma unroll
              for (int ni=0; ni<2; ni++){
                  int c = ncol0 + ni*8 + tig*2;
                  CSE(r,   c  ) = acc[ni][0];
                  CSE(r,   c+1) = acc[ni][1];
                  CSE(r+8, c  ) = acc[ni][2];
                  CSE(r+8, c+1) = acc[ni][3];
              } }
        } else {
            for (int i = tid; i < 64*32; i += 256) Cs[i] = 0.f;
        }
        __syncthreads();

        // gate + state update; thread owns (b,hcol) pairs p=tid, p+256
        const float* gxs = gx + (size_t)s*BATCH*NG;
#pragma unroll
        for (int rep=0; rep<2; rep++){
            int p = tid + rep*256;
            int b = p >> 3, jj = p & 7;
            int hc = hcol0 + jj;
            float xi = CSE(b, jj     ) + gxs[(size_t)b*NG +        hc];
            float xf = CSE(b, 8 + jj ) + gxs[(size_t)b*NG + 1024 + hc];
            float xg = CSE(b, 16 + jj) + gxs[(size_t)b*NG + 2048 + hc];
            float xo = CSE(b, 24 + jj) + gxs[(size_t)b*NG + 3072 + hc];
            float iv = 1.f/(1.f + expf(-xi));
            float fv = 1.f/(1.f + expf(-xf));
            float gv = tanhf(xg);
            float ov = 1.f/(1.f + expf(-xo));
            float cprev = rep ? creg1 : creg0;
            float cnew  = fv*cprev + iv*gv;
            if (rep) creg1 = cnew; else creg0 = cnew;
            float hv = ov * tanhf(cnew);
            hsb[(size_t)s*BATCH*HID + (size_t)b*HID + hc] = __float2half(hv);
            if (s == SEQ-1){
                size_t o1 = (size_t)b*HID + hc;
                out[ 65536 + (size_t)layer*65536 + o1] = hv;   // h_n
                out[196608 + (size_t)layer*65536 + o1] = cnew; // c_n
                if (layer == 1) out[o1] = hv;                  // y = seq[:,-1,:]
            }
        }
        if (s < SEQ-1) grid_bar();
    }
#undef WHS
#undef ASB
#undef CSE
}

// ---------------- launch ----------------
extern "C" void kernel_launch(void* const* d_in, const int* in_sizes, int n_in,
                              void* d_out, int out_size){
    const float* x  = (const float*)d_in[0];
    const float* Wi = (const float*)d_in[1];
    const float* bi = (const float*)d_in[2];
    const float* Wh = (const float*)d_in[3];
    const float* bh = (const float*)d_in[4];
    float* out = (float*)d_out;

    const int SCAN_SMEM = 32*1032*2 + 2*64*40*2 + 64*32*4;  // 84480 bytes
    cudaFuncSetAttribute(k_scan, cudaFuncAttributeMaxDynamicSharedMemorySize, SCAN_SMEM);

    k_convx<<<(MROWS*HID)/256, 256>>>(x);
    k_convw<<<dim3(32,32,16), dim3(32,32)>>>(Wi, Wh);
    k_bias<<<32, 256>>>(bi, bh);

    for (int l = 0; l < 2; l++){
        k_gemm<<<dim3(NG/128, MROWS/128), 256>>>(l);
        k_scan<<<128, 256, SCAN_SMEM>>>(l, out);
    }
}

// round 2
// speedup vs baseline: 1.5812x; 1.5812x over previous
#include <cuda_runtime.h>
#include <cuda_fp16.h>
#include <cstdint>
#include <math.h>

// Problem constants
#define SEQ   512
#define BATCH 64
#define HID   1024
#define NG    4096            // 4*HID
#define MROWS (SEQ*BATCH)     // 32768

// ---------------- static device scratch (no allocs allowed) ----------------
__device__ float  d_gx [(size_t)SEQ*BATCH*NG];   // 512 MB, fp32 gate preacts
__device__ __half d_xh [(size_t)SEQ*BATCH*HID];  // x transposed to [s][b][h] fp16
__device__ __half d_hs0[(size_t)SEQ*BATCH*HID];  // layer-0 hidden sequence
__device__ __half d_hs1[(size_t)SEQ*BATCH*HID];  // layer-1 hidden sequence
__device__ __half d_wti[(size_t)2*NG*HID];       // Wi transposed: [l][n=g*H+h][d] fp16
__device__ __half d_wth[(size_t)2*NG*HID];       // Wh transposed: [l][n][d] fp16
__device__ float  d_biasT[2*NG];                 // bi + bh folded
__device__ unsigned d_barcnt;
__device__ unsigned d_bargen;

// ---------------- small PTX helpers ----------------
__device__ __forceinline__ void cpa16(void* s, const void* g){
    uint32_t sa = (uint32_t)__cvta_generic_to_shared(s);
    asm volatile("cp.async.cg.shared.global [%0],[%1],16;\n" :: "r"(sa), "l"(g));
}
#define CPCOMMIT() asm volatile("cp.async.commit_group;\n")
template<int N> __device__ __forceinline__ void cpwait(){
    asm volatile("cp.async.wait_group %0;\n" :: "n"(N));
}
__device__ __forceinline__ void mma16816(float* c, const uint32_t* a, const uint32_t* b){
    asm volatile(
        "mma.sync.aligned.m16n8k16.row.col.f32.f16.f16.f32 "
        "{%0,%1,%2,%3},{%4,%5,%6,%7},{%8,%9},{%0,%1,%2,%3};\n"
        : "+f"(c[0]), "+f"(c[1]), "+f"(c[2]), "+f"(c[3])
        : "r"(a[0]), "r"(a[1]), "r"(a[2]), "r"(a[3]), "r"(b[0]), "r"(b[1]));
}

// ---------------- converts ----------------
// x [B][S][H] f32  ->  xh [S][B][H] fp16
__global__ void k_convx(const float* __restrict__ x){
    size_t i = (size_t)blockIdx.x*256 + threadIdx.x;      // 33,554,432 total
    int h = (int)(i & 1023);
    size_t t = i >> 10;
    int s = (int)(t & 511);
    int b = (int)(t >> 9);
    d_xh[((size_t)s*BATCH + b)*HID + h] = __float2half(x[i]);
}

// Wi/Wh [l][g][d][h] f32 -> Wt [l][g*H+h][d] fp16 (transpose d<->h, tiled)
__global__ void k_convw(const float* __restrict__ Wi, const float* __restrict__ Wh){
    __shared__ float sm[32][33];
    int z   = blockIdx.z;
    int sel = z >> 3;          // 0 = Wi, 1 = Wh
    int l   = (z >> 2) & 1;
    int g   = z & 3;
    const float* src = (sel ? Wh : Wi) + ((size_t)(l*4 + g)) * 1024u * 1024u;
    __half* dst = (sel ? d_wth : d_wti) + ((size_t)l*NG + (size_t)g*1024) * 1024u;
    int d0 = blockIdx.x*32, h0 = blockIdx.y*32;
    sm[threadIdx.y][threadIdx.x] = src[(size_t)(d0+threadIdx.y)*1024 + (h0+threadIdx.x)];
    __syncthreads();
    dst[(size_t)(h0+threadIdx.y)*1024 + (d0+threadIdx.x)] = __float2half(sm[threadIdx.x][threadIdx.y]);
}

__global__ void k_bias(const float* __restrict__ bi, const float* __restrict__ bh){
    int i = blockIdx.x*256 + threadIdx.x;   // 8192
    d_biasT[i] = bi[i] + bh[i];
}

// ---------------- big input-projection GEMM ----------------
// C[MROWS][NG] = A[MROWS][1024] * W[n][k]^T + biasT   (A rows are (s,b))
__global__ void __launch_bounds__(256) k_gemm(int layer){
    const __half* __restrict__ Aptr = layer ? d_hs0 : d_xh;
    const __half* __restrict__ Wptr = d_wti + (size_t)layer*NG*HID;
    const float*  __restrict__ bias = d_biasT + layer*NG;
    float* __restrict__ Cout = d_gx;

    __shared__ __half As[2][128][40];
    __shared__ __half Bs[2][128][40];

    int tid = threadIdx.x, lane = tid & 31, w = tid >> 5;
    int grp = lane >> 2, tig = lane & 3;
    int wm = w & 1, wn = w >> 1;                 // 2 m-warps x 4 n-warps
    size_t m0 = (size_t)blockIdx.y*128, n0 = (size_t)blockIdx.x*128;

    float acc[4][4][4];
#pragma unroll
    for (int a=0;a<4;a++)
#pragma unroll
        for (int b=0;b<4;b++)
#pragma unroll
            for (int c=0;c<4;c++) acc[a][b][c] = 0.f;

#define GEMM_STAGE(BUF,KC) do{                                                   \
    _Pragma("unroll")                                                            \
    for (int rr=0; rr<2; rr++){                                                  \
        int idx = tid + rr*256; int row = idx>>2, seg = idx&3;                   \
        cpa16(&As[BUF][row][seg*8], Aptr + (m0+row)*HID + (KC)*32 + seg*8);      \
        cpa16(&Bs[BUF][row][seg*8], Wptr + (n0+row)*HID + (KC)*32 + seg*8);      \
    } }while(0)

    GEMM_STAGE(0,0); CPCOMMIT();
    for (int kc=0; kc<32; kc++){
        if (kc+1 < 32){ GEMM_STAGE((kc+1)&1, kc+1); CPCOMMIT(); cpwait<1>(); }
        else          { cpwait<0>(); }
        __syncthreads();
        int buf = kc & 1;
#pragma unroll
        for (int kk=0; kk<2; kk++){
            uint32_t ar[4][4], br[4][2];
            int k0 = kk*16 + tig*2;
#pragma unroll
            for (int mi=0; mi<4; mi++){
                int r = wm*64 + mi*16 + grp;
                ar[mi][0] = *(const uint32_t*)&As[buf][r  ][k0  ];
                ar[mi][1] = *(const uint32_t*)&As[buf][r+8][k0  ];
                ar[mi][2] = *(const uint32_t*)&As[buf][r  ][k0+8];
                ar[mi][3] = *(const uint32_t*)&As[buf][r+8][k0+8];
            }
#pragma unroll
            for (int ni=0; ni<4; ni++){
                int n = wn*32 + ni*8 + grp;
                br[ni][0] = *(const uint32_t*)&Bs[buf][n][k0  ];
                br[ni][1] = *(const uint32_t*)&Bs[buf][n][k0+8];
            }
#pragma unroll
            for (int mi=0; mi<4; mi++)
#pragma unroll
                for (int ni=0; ni<4; ni++)
                    mma16816(acc[mi][ni], ar[mi], br[ni]);
        }
        __syncthreads();
    }
#undef GEMM_STAGE

#pragma unroll
    for (int mi=0; mi<4; mi++){
        size_t r = m0 + wm*64 + mi*16 + grp;
#pragma unroll
        for (int ni=0; ni<4; ni++){
            size_t n = n0 + wn*32 + ni*8 + tig*2;
            float b0 = bias[n], b1 = bias[n+1];
            Cout[ r   *NG + n  ] = acc[mi][ni][0] + b0;
            Cout[ r   *NG + n+1] = acc[mi][ni][1] + b1;
            Cout[(r+8)*NG + n  ] = acc[mi][ni][2] + b0;
            Cout[(r+8)*NG + n+1] = acc[mi][ni][3] + b1;
        }
    }
}

// ---------------- persistent recurrent scan ----------------
__device__ __forceinline__ void grid_bar(){
    __syncthreads();
    if (threadIdx.x == 0){
        __threadfence();
        unsigned g = *(volatile unsigned*)&d_bargen;
        unsigned t = atomicAdd(&d_barcnt, 1u);
        if (t == gridDim.x - 1){
            d_barcnt = 0;
            __threadfence();
            atomicExch(&d_bargen, g + 1u);
        } else {
            while (*(volatile unsigned*)&d_bargen == g) { }  // hard spin: L2 poll ~300cyc
        }
        __threadfence();
    }
    __syncthreads();
}

// 128 CTAs x 256 threads. CTA owns hcols [cta*8, cta*8+8) across all 4 gates.
// Wh slice (32 n-rows x 1024 k, 66KB) AND the full previous hidden state
// (64 x 1024 fp16, 132KB) are both SMEM-resident; h is reloaded per step in
// 4 k-ordered cp.async commit groups, computed progressively (5 block
// barriers per step instead of ~66).
__global__ void __launch_bounds__(256) k_scan(int layer, float* __restrict__ out){
    extern __shared__ char smem[];
    __half* Whs = (__half*)smem;                                  // [32][1032]
    __half* Hs  = (__half*)(smem + 32*1032*2);                    // [64][1032]
    float*  Cs  = (float*)(smem + 32*1032*2 + 64*1032*2);         // [64][32]
#define WHS(j,k)   Whs[(j)*1032 + (k)]
#define HS(r,k)    Hs[(r)*1032 + (k)]
#define CSE(r,c)   Cs[(r)*32 + (c)]

    const float*  __restrict__ gx  = d_gx;
    const __half* __restrict__ Whl = d_wth + (size_t)layer*NG*HID;
    __half* __restrict__ hsb = layer ? d_hs1 : d_hs0;

    int tid = threadIdx.x, lane = tid & 31, w = tid >> 5;
    int grp = lane >> 2, tig = lane & 3;
    int mrow0 = (w & 3)*16;            // 4 m-warps of 16 rows
    int ncol0 = (w >> 2)*16;           // 2 n-warps of 16 cols
    int hcol0 = blockIdx.x * 8;

    // Load resident Wh slice: row j -> n = (j>>3)*1024 + hcol0 + (j&7)
    for (int idx = tid; idx < 32*128; idx += 256){
        int j = idx >> 7, seg = idx & 127;
        int gate = j >> 3, hc = hcol0 + (j & 7);
        const __half* srcr = Whl + ((size_t)gate*1024 + hc)*1024;
        *(float4*)&WHS(j, seg*8) = *(const float4*)&srcr[seg*8];
    }
    __syncthreads();

    float creg0 = 0.f, creg1 = 0.f;

    // gate-update coordinates for this thread (2 reps: p = tid, tid+256)
    int b0r = tid >> 3,           jj0 = tid & 7;
    int b1r = (tid + 256) >> 3,   jj1 = tid & 7;
    int hc0 = hcol0 + jj0, hc1 = hcol0 + jj1;

    for (int s = 0; s < SEQ; s++){
        // -- prefetch this step's gx into registers (hides DRAM under MMA) --
        const float* gxs = gx + (size_t)s*BATCH*NG;
        float p0i = gxs[(size_t)b0r*NG +        hc0];
        float p0f = gxs[(size_t)b0r*NG + 1024 + hc0];
        float p0g = gxs[(size_t)b0r*NG + 2048 + hc0];
        float p0o = gxs[(size_t)b0r*NG + 3072 + hc0];
        float p1i = gxs[(size_t)b1r*NG +        hc1];
        float p1f = gxs[(size_t)b1r*NG + 1024 + hc1];
        float p1g = gxs[(size_t)b1r*NG + 2048 + hc1];
        float p1o = gxs[(size_t)b1r*NG + 3072 + hc1];

        if (s > 0){
            const __half* hprev = hsb + (size_t)(s-1)*BATCH*HID;
            // issue all 4 k-groups (each: 64 rows x 256 k = 2048 16B chunks)
#pragma unroll
            for (int g = 0; g < 4; g++){
#pragma unroll
                for (int i = 0; i < 8; i++){
                    int idx = i*256 + tid;
                    int row = idx >> 5, ch = idx & 31;
                    cpa16(&HS(row, g*256 + ch*8),
                          hprev + (size_t)row*HID + g*256 + ch*8);
                }
                CPCOMMIT();
            }

            float acc[2][4];
#pragma unroll
            for (int ni=0; ni<2; ni++)
#pragma unroll
                for (int c=0; c<4; c++) acc[ni][c] = 0.f;

#define COMP_KC(KC) do{                                                        \
    _Pragma("unroll")                                                          \
    for (int kk=0; kk<2; kk++){                                                \
        int k0 = (KC)*32 + kk*16 + tig*2;                                      \
        uint32_t ar[4], br[2];                                                 \
        ar[0] = *(const uint32_t*)&HS(mrow0+grp,   k0  );                      \
        ar[1] = *(const uint32_t*)&HS(mrow0+grp+8, k0  );                      \
        ar[2] = *(const uint32_t*)&HS(mrow0+grp,   k0+8);                      \
        ar[3] = *(const uint32_t*)&HS(mrow0+grp+8, k0+8);                      \
        _Pragma("unroll")                                                      \
        for (int ni=0; ni<2; ni++){                                            \
            int j = ncol0 + ni*8 + grp;                                        \
            br[0] = *(const uint32_t*)&WHS(j, k0  );                           \
            br[1] = *(const uint32_t*)&WHS(j, k0+8);                           \
            mma16816(acc[ni], ar, br);                                         \
        }                                                                      \
    } }while(0)

#pragma unroll
            for (int g = 0; g < 4; g++){
                if      (g == 0) cpwait<3>();
                else if (g == 1) cpwait<2>();
                else if (g == 2) cpwait<1>();
                else             cpwait<0>();
                __syncthreads();
#pragma unroll
                for (int kc8 = 0; kc8 < 8; kc8++)
                    COMP_KC(g*8 + kc8);
            }
#undef COMP_KC

            { int r = mrow0 + grp;
#pragma unroll
              for (int ni=0; ni<2; ni++){
                  int c = ncol0 + ni*8 + tig*2;
                  CSE(r,   c  ) = acc[ni][0];
                  CSE(r,   c+1) = acc[ni][1];
                  CSE(r+8, c  ) = acc[ni][2];
                  CSE(r+8, c+1) = acc[ni][3];
              } }
        } else {
            for (int i = tid; i < 64*32; i += 256) Cs[i] = 0.f;
        }
        __syncthreads();

        // gate + state update; thread owns (b,hcol) pairs p=tid, p+256
        {
            float xi = CSE(b0r, jj0     ) + p0i;
            float xf = CSE(b0r, 8 + jj0 ) + p0f;
            float xg = CSE(b0r, 16 + jj0) + p0g;
            float xo = CSE(b0r, 24 + jj0) + p0o;
            float iv = 1.f/(1.f + expf(-xi));
            float fv = 1.f/(1.f + expf(-xf));
            float gv = tanhf(xg);
            float ov = 1.f/(1.f + expf(-xo));
            float cnew = fv*creg0 + iv*gv;
            creg0 = cnew;
            float hv = ov * tanhf(cnew);
            hsb[(size_t)s*BATCH*HID + (size_t)b0r*HID + hc0] = __float2half(hv);
            if (s == SEQ-1){
                size_t o1 = (size_t)b0r*HID + hc0;
                out[ 65536 + (size_t)layer*65536 + o1] = hv;   // h_n
                out[196608 + (size_t)layer*65536 + o1] = cnew; // c_n
                if (layer == 1) out[o1] = hv;                  // y = seq[:,-1,:]
            }
        }
        {
            float xi = CSE(b1r, jj1     ) + p1i;
            float xf = CSE(b1r, 8 + jj1 ) + p1f;
            float xg = CSE(b1r, 16 + jj1) + p1g;
            float xo = CSE(b1r, 24 + jj1) + p1o;
            float iv = 1.f/(1.f + expf(-xi));
            float fv = 1.f/(1.f + expf(-xf));
            float gv = tanhf(xg);
            float ov = 1.f/(1.f + expf(-xo));
            float cnew = fv*creg1 + iv*gv;
            creg1 = cnew;
            float hv = ov * tanhf(cnew);
            hsb[(size_t)s*BATCH*HID + (size_t)b1r*HID + hc1] = __float2half(hv);
            if (s == SEQ-1){
                size_t o1 = (size_t)b1r*HID + hc1;
                out[ 65536 + (size_t)layer*65536 + o1] = hv;   // h_n
                out[196608 + (size_t)layer*65536 + o1] = cnew; // c_n
                if (layer == 1) out[o1] = hv;                  // y = seq[:,-1,:]
            }
        }
        if (s < SEQ-1) grid_bar();
    }
#undef WHS
#undef HS
#undef CSE
}

// ---------------- launch ----------------
extern "C" void kernel_launch(void* const* d_in, const int* in_sizes, int n_in,
                              void* d_out, int out_size){
    const float* x  = (const float*)d_in[0];
    const float* Wi = (const float*)d_in[1];
    const float* bi = (const float*)d_in[2];
    const float* Wh = (const float*)d_in[3];
    const float* bh = (const float*)d_in[4];
    float* out = (float*)d_out;

    const int SCAN_SMEM = 32*1032*2 + 64*1032*2 + 64*32*4;  // 206,336 bytes
    cudaFuncSetAttribute(k_scan, cudaFuncAttributeMaxDynamicSharedMemorySize, SCAN_SMEM);

    k_convx<<<(MROWS*HID)/256, 256>>>(x);
    k_convw<<<dim3(32,32,16), dim3(32,32)>>>(Wi, Wh);
    k_bias<<<32, 256>>>(bi, bh);

    for (int l = 0; l < 2; l++){
        k_gemm<<<dim3(NG/128, MROWS/128), 256>>>(l);
        k_scan<<<128, 256, SCAN_SMEM>>>(l, out);
    }
}

// round 4
// speedup vs baseline: 1.9747x; 1.2488x over previous
#include <cuda_runtime.h>
#include <cuda.h>
#include <cuda_fp16.h>
#include <cstdint>
#include <math.h>

// Problem constants
#define SEQ   512
#define BATCH 64
#define HID   1024
#define NG    4096            // 4*HID
#define MROWS (SEQ*BATCH)     // 32768

// ---------------- static device scratch (no allocs allowed) ----------------
__device__ float  d_gx [(size_t)SEQ*BATCH*NG];   // fp32 gate preacts
__device__ __half d_xh [(size_t)SEQ*BATCH*HID];  // [s][b][k] fp16 (x, then h0^T for gemm1)
__device__ __half d_hs0[(size_t)SEQ*BATCH*HID];  // layer-0 hidden, [s][k][b] fp16
__device__ __half d_hs1[(size_t)SEQ*BATCH*HID];  // layer-1 hidden, [s][k][b] fp16
__device__ __half d_wti[(size_t)2*NG*HID];       // Wi transposed: [l][n][k] fp16
__device__ __half d_wth[(size_t)2*NG*HID];       // Wh transposed: [l][n][k] fp16
__device__ float  d_biasT[2*NG];                 // bi + bh folded
__device__ unsigned d_barcnt;
__device__ unsigned d_bargen;

// ---------------- PTX helpers ----------------
__device__ __forceinline__ void cpa16(void* s, const void* g){
    uint32_t sa = (uint32_t)__cvta_generic_to_shared(s);
    asm volatile("cp.async.cg.shared.global [%0],[%1],16;\n" :: "r"(sa), "l"(g));
}
#define CPCOMMIT() asm volatile("cp.async.commit_group;\n")
template<int N> __device__ __forceinline__ void cpwait(){
    asm volatile("cp.async.wait_group %0;\n" :: "n"(N));
}
__device__ __forceinline__ void mma16816(float* c, const uint32_t* a, const uint32_t* b){
    asm volatile(
        "mma.sync.aligned.m16n8k16.row.col.f32.f16.f16.f32 "
        "{%0,%1,%2,%3},{%4,%5,%6,%7},{%8,%9},{%0,%1,%2,%3};\n"
        : "+f"(c[0]), "+f"(c[1]), "+f"(c[2]), "+f"(c[3])
        : "r"(a[0]), "r"(a[1]), "r"(a[2]), "r"(a[3]), "r"(b[0]), "r"(b[1]));
}
#define LDSM_X4_T(r0,r1,r2,r3,a) \
    asm volatile("ldmatrix.sync.aligned.m8n8.x4.trans.shared.b16 {%0,%1,%2,%3}, [%4];" \
        : "=r"(r0), "=r"(r1), "=r"(r2), "=r"(r3) : "r"(a))

// ---- TMA / mbarrier (sm_90 baseline PTX, legal on compute_100) ----
#define MBARRIER_INIT(addr, cnt) \
    asm volatile("mbarrier.init.shared.b64 [%0], %1;" :: "r"((uint32_t)(addr)), "r"((uint32_t)(cnt)) : "memory")
#define MBARRIER_EXPECT_TX(addr, bytes) \
    asm volatile("mbarrier.arrive.expect_tx.shared.b64 _, [%0], %1;" :: "r"((uint32_t)(addr)), "r"((uint32_t)(bytes)) : "memory")
#define MBARRIER_WAIT_PARITY(addr, parity) do {                                   \
    uint32_t _mb = (uint32_t)(addr); uint32_t _ph = (uint32_t)(parity);           \
    asm volatile(                                                                  \
        "{\n\t.reg .pred P1;\n\t"                                                  \
        "WAIT_LP_%=:\n\t"                                                          \
        "mbarrier.try_wait.parity.acquire.cta.shared::cta.b64 P1, [%0], %1, 0x989680;\n\t" \
        "@P1 bra.uni WAIT_DN_%=;\n\t"                                              \
        "bra.uni WAIT_LP_%=;\n\t"                                                  \
        "WAIT_DN_%=:\n\t}"                                                         \
        :: "r"(_mb), "r"(_ph) : "memory");                                         \
} while(0)
#define TMA_LOAD_3D(smem_addr, tmap, cx, cy, cz, mbar) \
    asm volatile( \
        "cp.async.bulk.tensor.3d.shared::cta.global.tile.mbarrier::complete_tx::bytes " \
        "[%0], [%1, {%2, %3, %4}], [%5];" \
        :: "r"((uint32_t)(smem_addr)), "l"(tmap), "r"((int)(cx)), "r"((int)(cy)), "r"((int)(cz)), \
           "r"((uint32_t)(mbar)) : "memory")

// ---------------- converts ----------------
__global__ void k_convx(const float* __restrict__ x){
    size_t i = (size_t)blockIdx.x*256 + threadIdx.x;
    int h = (int)(i & 1023);
    size_t t = i >> 10;
    int s = (int)(t & 511);
    int b = (int)(t >> 9);
    d_xh[((size_t)s*BATCH + b)*HID + h] = __float2half(x[i]);
}

__global__ void k_convw(const float* __restrict__ Wi, const float* __restrict__ Wh){
    __shared__ float sm[32][33];
    int z   = blockIdx.z;
    int sel = z >> 3;
    int l   = (z >> 2) & 1;
    int g   = z & 3;
    const float* src = (sel ? Wh : Wi) + ((size_t)(l*4 + g)) * 1024u * 1024u;
    __half* dst = (sel ? d_wth : d_wti) + ((size_t)l*NG + (size_t)g*1024) * 1024u;
    int d0 = blockIdx.x*32, h0 = blockIdx.y*32;
    sm[threadIdx.y][threadIdx.x] = src[(size_t)(d0+threadIdx.y)*1024 + (h0+threadIdx.x)];
    __syncthreads();
    dst[(size_t)(h0+threadIdx.y)*1024 + (d0+threadIdx.x)] = __float2half(sm[threadIdx.x][threadIdx.y]);
}

__global__ void k_bias(const float* __restrict__ bi, const float* __restrict__ bh){
    int i = blockIdx.x*256 + threadIdx.x;
    d_biasT[i] = bi[i] + bh[i];
}

// hs0 [s][k][b] -> d_xh [s][b][k]  (for layer-1 input GEMM)
__global__ void k_trans(){
    __shared__ __half sm[32][65];
    int s  = blockIdx.x;
    int k0 = blockIdx.y * 32;
    const __half* src = d_hs0 + (size_t)s*65536;
    __half* dst = d_xh + (size_t)s*65536;
    int tx = threadIdx.x, ty = threadIdx.y;
#pragma unroll
    for (int bh = 0; bh < 2; bh++){
        sm[ty][tx] = src[(size_t)(k0+ty)*64 + bh*32 + tx];
        __syncthreads();
        dst[(size_t)(bh*32+ty)*1024 + k0 + tx] = sm[tx][ty];
        __syncthreads();
    }
}

// ---------------- big input-projection GEMM ----------------
__global__ void __launch_bounds__(256) k_gemm(int layer){
    const __half* __restrict__ Aptr = d_xh;     // x (l=0) or transposed h0 (l=1)
    const __half* __restrict__ Wptr = d_wti + (size_t)layer*NG*HID;
    const float*  __restrict__ bias = d_biasT + layer*NG;
    float* __restrict__ Cout = d_gx;

    __shared__ __half As[2][128][40];
    __shared__ __half Bs[2][128][40];

    int tid = threadIdx.x, lane = tid & 31, w = tid >> 5;
    int grp = lane >> 2, tig = lane & 3;
    int wm = w & 1, wn = w >> 1;
    size_t m0 = (size_t)blockIdx.y*128, n0 = (size_t)blockIdx.x*128;

    float acc[4][4][4];
#pragma unroll
    for (int a=0;a<4;a++)
#pragma unroll
        for (int b=0;b<4;b++)
#pragma unroll
            for (int c=0;c<4;c++) acc[a][b][c] = 0.f;

#define GEMM_STAGE(BUF,KC) do{                                                   \
    _Pragma("unroll")                                                            \
    for (int rr=0; rr<2; rr++){                                                  \
        int idx = tid + rr*256; int row = idx>>2, seg = idx&3;                   \
        cpa16(&As[BUF][row][seg*8], Aptr + (m0+row)*HID + (KC)*32 + seg*8);      \
        cpa16(&Bs[BUF][row][seg*8], Wptr + (n0+row)*HID + (KC)*32 + seg*8);      \
    } }while(0)

    GEMM_STAGE(0,0); CPCOMMIT();
    for (int kc=0; kc<32; kc++){
        if (kc+1 < 32){ GEMM_STAGE((kc+1)&1, kc+1); CPCOMMIT(); cpwait<1>(); }
        else          { cpwait<0>(); }
        __syncthreads();
        int buf = kc & 1;
#pragma unroll
        for (int kk=0; kk<2; kk++){
            uint32_t ar[4][4], br[4][2];
            int k0 = kk*16 + tig*2;
#pragma unroll
            for (int mi=0; mi<4; mi++){
                int r = wm*64 + mi*16 + grp;
                ar[mi][0] = *(const uint32_t*)&As[buf][r  ][k0  ];
                ar[mi][1] = *(const uint32_t*)&As[buf][r+8][k0  ];
                ar[mi][2] = *(const uint32_t*)&As[buf][r  ][k0+8];
                ar[mi][3] = *(const uint32_t*)&As[buf][r+8][k0+8];
            }
#pragma unroll
            for (int ni=0; ni<4; ni++){
                int n = wn*32 + ni*8 + grp;
                br[ni][0] = *(const uint32_t*)&Bs[buf][n][k0  ];
                br[ni][1] = *(const uint32_t*)&Bs[buf][n][k0+8];
            }
#pragma unroll
            for (int mi=0; mi<4; mi++)
#pragma unroll
                for (int ni=0; ni<4; ni++)
                    mma16816(acc[mi][ni], ar[mi], br[ni]);
        }
        __syncthreads();
    }
#undef GEMM_STAGE

#pragma unroll
    for (int mi=0; mi<4; mi++){
        size_t r = m0 + wm*64 + mi*16 + grp;
#pragma unroll
        for (int ni=0; ni<4; ni++){
            size_t n = n0 + wn*32 + ni*8 + tig*2;
            float b0 = bias[n], b1 = bias[n+1];
            Cout[ r   *NG + n  ] = acc[mi][ni][0] + b0;
            Cout[ r   *NG + n+1] = acc[mi][ni][1] + b1;
            Cout[(r+8)*NG + n  ] = acc[mi][ni][2] + b0;
            Cout[(r+8)*NG + n+1] = acc[mi][ni][3] + b1;
        }
    }
}

// ---------------- persistent recurrent scan ----------------
__device__ __forceinline__ void grid_bar(){
    __syncthreads();
    if (threadIdx.x == 0){
        __threadfence();
        unsigned g = *(volatile unsigned*)&d_bargen;
        unsigned t = atomicAdd(&d_barcnt, 1u);
        if (t == gridDim.x - 1){
            d_barcnt = 0;
            __threadfence();
            atomicExch(&d_bargen, g + 1u);
        } else {
            while (*(volatile unsigned*)&d_bargen == g) { }
        }
        __threadfence();
    }
    __syncthreads();
}

// 128 CTAs x 256 threads (8 warps). CTA owns hcols [cta*8, cta*8+8) across the
// 4 gates (N=32). Warp w owns k-slice [w*128, w*128+128):
//   - Wh fragments register-resident (loaded once from global)
//   - h[s-1] slice arrives via TMA (SW128, [k][b] rows of 128B) -> ldmatrix.x4.trans
//   - per-warp partial D[64x32] f32 -> smem reduction -> gate update
__global__ void __launch_bounds__(256,1) k_scan(int layer, float* __restrict__ out,
        const __grid_constant__ CUtensorMap mH)
{
    extern __shared__ __align__(1024) char dsm[];
    uint32_t raw  = (uint32_t)__cvta_generic_to_shared(dsm);
    uint32_t base = (raw + 1023u) & ~1023u;
    char* gb = dsm + (base - raw);
    uint32_t mb = base;                       // 8 mbarriers (8B each)
    uint32_t sA = base + 1024;                // 128KB: 8 slices x 16KB ([128k][128B])
    float* P  = (float*)(gb + 132096);        // 8 x [64][36] f32 partials (72KB)
    float* Cs = (float*)(gb + 205824);        // [64][36] f32 reduced

    const int tid  = threadIdx.x;
    const int lane = tid & 31, w = tid >> 5;
    const int grp  = lane >> 2, tig = lane & 3;
    const int hcol0 = blockIdx.x * 8;
    const __half* __restrict__ Whp = d_wth + (size_t)layer*NG*HID;
    __half* __restrict__ hsb = layer ? d_hs1 : d_hs0;

    if (tid < 8) MBARRIER_INIT(mb + tid*8, 1);

    // register-resident B fragments: brf[nt][kt][2]
    uint32_t brf[4][8][2];
#pragma unroll
    for (int nt = 0; nt < 4; nt++){
        const __half* rp = Whp + (size_t)(nt*1024 + hcol0 + grp)*1024 + w*128 + tig*2;
#pragma unroll
        for (int kt = 0; kt < 8; kt++){
            brf[nt][kt][0] = *(const uint32_t*)(rp + kt*16);
            brf[nt][kt][1] = *(const uint32_t*)(rp + kt*16 + 8);
        }
    }

    // ldmatrix lane constants (source [k][m], SW128 swizzle: col ^ ((k&7)<<4))
    const int q = lane >> 3, iq = lane & 7;
    const uint32_t rowoff = (uint32_t)((((q>>1)*8) + iq) * 128);
    const uint32_t cadd   = (uint32_t)((q & 1) * 16);
    const uint32_t ixor   = (uint32_t)(iq << 4);
    const uint32_t sAw    = sA + (uint32_t)w * 16384u;

    float creg0 = 0.f, creg1 = 0.f;
    const int b0r = tid >> 3, jj = tid & 7;
    const int b1r = 32 + b0r;
    const int hc  = hcol0 + jj;

    __syncthreads();

    for (int s = 0; s < SEQ; s++){
        const float* gxs = d_gx + (size_t)s*BATCH*NG;
        float p0i = gxs[(size_t)b0r*NG +        hc];
        float p0f = gxs[(size_t)b0r*NG + 1024 + hc];
        float p0g = gxs[(size_t)b0r*NG + 2048 + hc];
        float p0o = gxs[(size_t)b0r*NG + 3072 + hc];
        float p1i = gxs[(size_t)b1r*NG +        hc];
        float p1f = gxs[(size_t)b1r*NG + 1024 + hc];
        float p1g = gxs[(size_t)b1r*NG + 2048 + hc];
        float p1o = gxs[(size_t)b1r*NG + 3072 + hc];

        if (s > 0){
            MBARRIER_WAIT_PARITY(mb + w*8, (s-1)&1);
            float acc[4][4][4];
#pragma unroll
            for (int a=0;a<4;a++)
#pragma unroll
                for (int b=0;b<4;b++)
#pragma unroll
                    for (int c=0;c<4;c++) acc[a][b][c] = 0.f;

#pragma unroll
            for (int kt = 0; kt < 8; kt++){
                uint32_t rowk = sAw + (uint32_t)(kt*2048) + rowoff;
#pragma unroll
                for (int mt = 0; mt < 4; mt++){
                    uint32_t addr = rowk + (((uint32_t)(mt*32) + cadd) ^ ixor);
                    uint32_t a0,a1,a2,a3;
                    LDSM_X4_T(a0,a1,a2,a3, addr);
                    uint32_t ar[4] = {a0,a1,a2,a3};
#pragma unroll
                    for (int nt = 0; nt < 4; nt++)
                        mma16816(acc[mt][nt], ar, brf[nt][kt]);
                }
            }
            // partial store: P[w][m][n], row stride 36 floats
            float* Pw = P + w*2304;
#pragma unroll
            for (int mt = 0; mt < 4; mt++){
                int m = mt*16 + grp;
#pragma unroll
                for (int nt = 0; nt < 4; nt++){
                    int n = nt*8 + tig*2;
                    *(float2*)(Pw + (size_t)m*36 + n)     = make_float2(acc[mt][nt][0], acc[mt][nt][1]);
                    *(float2*)(Pw + (size_t)(m+8)*36 + n) = make_float2(acc[mt][nt][2], acc[mt][nt][3]);
                }
            }
        }
        __syncthreads();

        if (s > 0){
            // cross-warp reduce: thread t owns row m=t>>2, cols (t&3)*8..+8
            int m = tid >> 2, nb = (tid & 3)*8;
            float r0=0,r1=0,r2=0,r3=0,r4=0,r5=0,r6=0,r7=0;
#pragma unroll
            for (int ww = 0; ww < 8; ww++){
                const float4* pp = (const float4*)(P + ww*2304 + m*36 + nb);
                float4 x = pp[0], y = pp[1];
                r0+=x.x; r1+=x.y; r2+=x.z; r3+=x.w;
                r4+=y.x; r5+=y.y; r6+=y.z; r7+=y.w;
            }
            *(float4*)(Cs + m*36 + nb)     = make_float4(r0,r1,r2,r3);
            *(float4*)(Cs + m*36 + nb + 4) = make_float4(r4,r5,r6,r7);
        } else {
            for (int i = tid; i < 2304; i += 256) Cs[i] = 0.f;
        }
        __syncthreads();

        // gate + state update (thread handles (b0r, jj) and (b1r, jj))
        {
            float xi = Cs[b0r*36 +      jj] + p0i;
            float xf = Cs[b0r*36 +  8 + jj] + p0f;
            float xg = Cs[b0r*36 + 16 + jj] + p0g;
            float xo = Cs[b0r*36 + 24 + jj] + p0o;
            float iv = 1.f/(1.f + expf(-xi));
            float fv = 1.f/(1.f + expf(-xf));
            float gv = tanhf(xg);
            float ov = 1.f/(1.f + expf(-xo));
            float cn = fv*creg0 + iv*gv;
            creg0 = cn;
            float hv = ov * tanhf(cn);
            hsb[(size_t)s*65536 + (size_t)hc*64 + b0r] = __float2half(hv);
            if (s == SEQ-1){
                size_t o1 = (size_t)b0r*HID + hc;
                out[ 65536 + (size_t)layer*65536 + o1] = hv;
                out[196608 + (size_t)layer*65536 + o1] = cn;
                if (layer == 1) out[o1] = hv;
            }
        }
        {
            float xi = Cs[b1r*36 +      jj] + p1i;
            float xf = Cs[b1r*36 +  8 + jj] + p1f;
            float xg = Cs[b1r*36 + 16 + jj] + p1g;
            float xo = Cs[b1r*36 + 24 + jj] + p1o;
            float iv = 1.f/(1.f + expf(-xi));
            float fv = 1.f/(1.f + expf(-xf));
            float gv = tanhf(xg);
            float ov = 1.f/(1.f + expf(-xo));
            float cn = fv*creg1 + iv*gv;
            creg1 = cn;
            float hv = ov * tanhf(cn);
            hsb[(size_t)s*65536 + (size_t)hc*64 + b1r] = __float2half(hv);
            if (s == SEQ-1){
                size_t o1 = (size_t)b1r*HID + hc;
                out[ 65536 + (size_t)layer*65536 + o1] = hv;
                out[196608 + (size_t)layer*65536 + o1] = cn;
                if (layer == 1) out[o1] = hv;
            }
        }

        if (s < SEQ-1){
            grid_bar();                        // h[s] now globally visible
            if (lane == 0){                    // refill own slice for step s+1
                MBARRIER_EXPECT_TX(mb + w*8, 16384);
                TMA_LOAD_3D(sAw, &mH, 0, w*128, s, mb + w*8);
            }
        }
    }
}

// ---------------- host: tensormap encode + launch ----------------
typedef CUresult (*PFN_encTiled)(CUtensorMap*, CUtensorMapDataType, cuuint32_t, void*,
                                 const cuuint64_t*, const cuuint64_t*, const cuuint32_t*,
                                 const cuuint32_t*, CUtensorMapInterleave, CUtensorMapSwizzle,
                                 CUtensorMapL2promotion, CUtensorMapFloatOOBfill);

static void enc_map_h(CUtensorMap* m, void* g){
    static PFN_encTiled fn = nullptr;
    if (!fn){
        cudaDriverEntryPointQueryResult qr;
        cudaGetDriverEntryPointByVersion("cuTensorMapEncodeTiled", (void**)&fn,
                                         12000, cudaEnableDefault, &qr);
    }
    cuuint64_t dims[3] = { 64, 1024, 512 };           // (b, k, s)
    cuuint64_t st[2]   = { 128ull, 131072ull };       // k stride 128B, s stride 128KB
    cuuint32_t box[3]  = { 64, 128, 1 };              // one warp k-slice
    cuuint32_t es[3]   = { 1, 1, 1 };
    fn(m, CU_TENSOR_MAP_DATA_TYPE_FLOAT16, 3, g, dims, st, box, es,
       CU_TENSOR_MAP_INTERLEAVE_NONE, CU_TENSOR_MAP_SWIZZLE_128B,
       CU_TENSOR_MAP_L2_PROMOTION_L2_128B, CU_TENSOR_MAP_FLOAT_OOB_FILL_NONE);
}

extern "C" void kernel_launch(void* const* d_in, const int* in_sizes, int n_in,
                              void* d_out, int out_size){
    const float* x  = (const float*)d_in[0];
    const float* Wi = (const float*)d_in[1];
    const float* bi = (const float*)d_in[2];
    const float* Wh = (const float*)d_in[3];
    const float* bh = (const float*)d_in[4];
    float* out = (float*)d_out;

    void *p_hs0, *p_hs1;
    cudaGetSymbolAddress(&p_hs0, d_hs0);
    cudaGetSymbolAddress(&p_hs1, d_hs1);

    CUtensorMap mH0, mH1;
    enc_map_h(&mH0, p_hs0);
    enc_map_h(&mH1, p_hs1);

    const int SCAN_SMEM = 1024 + 131072 + 73728 + 9216 + 1024;  // 216,064 B
    cudaFuncSetAttribute(k_scan, cudaFuncAttributeMaxDynamicSharedMemorySize, SCAN_SMEM);

    k_convx<<<(MROWS*HID)/256, 256>>>(x);
    k_convw<<<dim3(32,32,16), dim3(32,32)>>>(Wi, Wh);
    k_bias<<<32, 256>>>(bi, bh);

    k_gemm<<<dim3(NG/128, MROWS/128), 256>>>(0);
    k_scan<<<128, 256, SCAN_SMEM>>>(0, out, mH0);
    k_trans<<<dim3(512, 32), dim3(32, 32)>>>();
    k_gemm<<<dim3(NG/128, MROWS/128), 256>>>(1);
    k_scan<<<128, 256, SCAN_SMEM>>>(1, out, mH1);
}

// round 6
// speedup vs baseline: 2.3743x; 1.2024x over previous
#include <cuda_runtime.h>
#include <cuda.h>
#include <cuda_fp16.h>
#include <cstdint>
#include <math.h>

// Problem constants
#define SEQ   512
#define BATCH 64
#define HID   1024
#define NG    4096            // 4*HID
#define MROWS (SEQ*BATCH)     // 32768

// ---------------- static device scratch (no allocs allowed) ----------------
__device__ float  d_gx [(size_t)SEQ*BATCH*NG];   // fp32 gate preacts
__device__ __half d_xh [(size_t)SEQ*BATCH*HID];  // [s][b][k] fp16 (x, then h0^T for gemm1)
__device__ __half d_hs0[(size_t)SEQ*BATCH*HID];  // layer-0 hidden, [s][k][b] fp16
__device__ __half d_hs1[(size_t)SEQ*BATCH*HID];  // layer-1 hidden, [s][k][b] fp16
__device__ __half d_wti[(size_t)2*NG*HID];       // Wi transposed: [l][n][k] fp16
__device__ __half d_wth[(size_t)2*NG*HID];       // Wh transposed: [l][n][k] fp16
__device__ float  d_biasT[2*NG];                 // bi + bh folded
__device__ unsigned d_cnt[8*32];                 // 8 k-group counters, 128B apart

// ---------------- PTX helpers ----------------
__device__ __forceinline__ void cpa16(void* s, const void* g){
    uint32_t sa = (uint32_t)__cvta_generic_to_shared(s);
    asm volatile("cp.async.cg.shared.global [%0],[%1],16;\n" :: "r"(sa), "l"(g));
}
#define CPCOMMIT() asm volatile("cp.async.commit_group;\n")
template<int N> __device__ __forceinline__ void cpwait(){
    asm volatile("cp.async.wait_group %0;\n" :: "n"(N));
}
__device__ __forceinline__ void mma16816(float* c, const uint32_t* a, const uint32_t* b){
    asm volatile(
        "mma.sync.aligned.m16n8k16.row.col.f32.f16.f16.f32 "
        "{%0,%1,%2,%3},{%4,%5,%6,%7},{%8,%9},{%0,%1,%2,%3};\n"
        : "+f"(c[0]), "+f"(c[1]), "+f"(c[2]), "+f"(c[3])
        : "r"(a[0]), "r"(a[1]), "r"(a[2]), "r"(a[3]), "r"(b[0]), "r"(b[1]));
}
#define LDSM_X4_T(r0,r1,r2,r3,a) \
    asm volatile("ldmatrix.sync.aligned.m8n8.x4.trans.shared.b16 {%0,%1,%2,%3}, [%4];" \
        : "=r"(r0), "=r"(r1), "=r"(r2), "=r"(r3) : "r"(a))

__device__ __forceinline__ void red_release_add(unsigned* p){
    asm volatile("red.release.gpu.global.add.u32 [%0], 1;" :: "l"(p) : "memory");
}
__device__ __forceinline__ unsigned ld_acquire(const unsigned* p){
    unsigned v;
    asm volatile("ld.acquire.gpu.global.u32 %0, [%1];" : "=r"(v) : "l"(p) : "memory");
    return v;
}

// ---- TMA / mbarrier (sm_90 baseline PTX, legal on compute_100) ----
#define MBARRIER_INIT(addr, cnt) \
    asm volatile("mbarrier.init.shared.b64 [%0], %1;" :: "r"((uint32_t)(addr)), "r"((uint32_t)(cnt)) : "memory")
#define MBARRIER_EXPECT_TX(addr, bytes) \
    asm volatile("mbarrier.arrive.expect_tx.shared.b64 _, [%0], %1;" :: "r"((uint32_t)(addr)), "r"((uint32_t)(bytes)) : "memory")
#define MBARRIER_WAIT_PARITY(addr, parity) do {                                   \
    uint32_t _mb = (uint32_t)(addr); uint32_t _ph = (uint32_t)(parity);           \
    asm volatile(                                                                  \
        "{\n\t.reg .pred P1;\n\t"                                                  \
        "WAIT_LP_%=:\n\t"                                                          \
        "mbarrier.try_wait.parity.acquire.cta.shared::cta.b64 P1, [%0], %1, 0x989680;\n\t" \
        "@P1 bra.uni WAIT_DN_%=;\n\t"                                              \
        "bra.uni WAIT_LP_%=;\n\t"                                                  \
        "WAIT_DN_%=:\n\t}"                                                         \
        :: "r"(_mb), "r"(_ph) : "memory");                                         \
} while(0)
#define TMA_LOAD_3D(smem_addr, tmap, cx, cy, cz, mbar) \
    asm volatile( \
        "cp.async.bulk.tensor.3d.shared::cta.global.tile.mbarrier::complete_tx::bytes " \
        "[%0], [%1, {%2, %3, %4}], [%5];" \
        :: "r"((uint32_t)(smem_addr)), "l"(tmap), "r"((int)(cx)), "r"((int)(cy)), "r"((int)(cz)), \
           "r"((uint32_t)(mbar)) : "memory")

// ---------------- converts ----------------
__global__ void k_convx(const float* __restrict__ x){
    size_t i = (size_t)blockIdx.x*256 + threadIdx.x;
    int h = (int)(i & 1023);
    size_t t = i >> 10;
    int s = (int)(t & 511);
    int b = (int)(t >> 9);
    d_xh[((size_t)s*BATCH + b)*HID + h] = __float2half(x[i]);
}

__global__ void k_convw(const float* __restrict__ Wi, const float* __restrict__ Wh){
    __shared__ float sm[32][33];
    int z   = blockIdx.z;
    int sel = z >> 3;
    int l   = (z >> 2) & 1;
    int g   = z & 3;
    const float* src = (sel ? Wh : Wi) + ((size_t)(l*4 + g)) * 1024u * 1024u;
    __half* dst = (sel ? d_wth : d_wti) + ((size_t)l*NG + (size_t)g*1024) * 1024u;
    int d0 = blockIdx.x*32, h0 = blockIdx.y*32;
    sm[threadIdx.y][threadIdx.x] = src[(size_t)(d0+threadIdx.y)*1024 + (h0+threadIdx.x)];
    __syncthreads();
    dst[(size_t)(h0+threadIdx.y)*1024 + (d0+threadIdx.x)] = __float2half(sm[threadIdx.x][threadIdx.y]);
}

__global__ void k_bias(const float* __restrict__ bi, const float* __restrict__ bh){
    int i = blockIdx.x*256 + threadIdx.x;
    d_biasT[i] = bi[i] + bh[i];
}

__global__ void k_zc(){ if (threadIdx.x < 8*32) d_cnt[threadIdx.x] = 0u; }

// hs0 [s][k][b] -> d_xh [s][b][k]  (for layer-1 input GEMM)
__global__ void k_trans(){
    __shared__ __half sm[32][65];
    int s  = blockIdx.x;
    int k0 = blockIdx.y * 32;
    const __half* src = d_hs0 + (size_t)s*65536;
    __half* dst = d_xh + (size_t)s*65536;
    int tx = threadIdx.x, ty = threadIdx.y;
#pragma unroll
    for (int bh = 0; bh < 2; bh++){
        sm[ty][tx] = src[(size_t)(k0+ty)*64 + bh*32 + tx];
        __syncthreads();
        dst[(size_t)(bh*32+ty)*1024 + k0 + tx] = sm[tx][ty];
        __syncthreads();
    }
}

// ---------------- big input-projection GEMM ----------------
__global__ void __launch_bounds__(256,2) k_gemm(int layer){
    const __half* __restrict__ Aptr = d_xh;     // x (l=0) or transposed h0 (l=1)
    const __half* __restrict__ Wptr = d_wti + (size_t)layer*NG*HID;
    const float*  __restrict__ bias = d_biasT + layer*NG;
    float* __restrict__ Cout = d_gx;

    __shared__ __half As[2][128][40];
    __shared__ __half Bs[2][128][40];

    int tid = threadIdx.x, lane = tid & 31, w = tid >> 5;
    int grp = lane >> 2, tig = lane & 3;
    int wm = w & 1, wn = w >> 1;
    size_t m0 = (size_t)blockIdx.y*128, n0 = (size_t)blockIdx.x*128;

    float acc[4][4][4];
#pragma unroll
    for (int a=0;a<4;a++)
#pragma unroll
        for (int b=0;b<4;b++)
#pragma unroll
            for (int c=0;c<4;c++) acc[a][b][c] = 0.f;

#define GEMM_STAGE(BUF,KC) do{                                                   \
    _Pragma("unroll")                                                            \
    for (int rr=0; rr<2; rr++){                                                  \
        int idx = tid + rr*256; int row = idx>>2, seg = idx&3;                   \
        cpa16(&As[BUF][row][seg*8], Aptr + (m0+row)*HID + (KC)*32 + seg*8);      \
        cpa16(&Bs[BUF][row][seg*8], Wptr + (n0+row)*HID + (KC)*32 + seg*8);      \
    } }while(0)

    GEMM_STAGE(0,0); CPCOMMIT();
    for (int kc=0; kc<32; kc++){
        if (kc+1 < 32){ GEMM_STAGE((kc+1)&1, kc+1); CPCOMMIT(); cpwait<1>(); }
        else          { cpwait<0>(); }
        __syncthreads();
        int buf = kc & 1;
#pragma unroll
        for (int kk=0; kk<2; kk++){
            uint32_t ar[4][4], br[4][2];
            int k0 = kk*16 + tig*2;
#pragma unroll
            for (int mi=0; mi<4; mi++){
                int r = wm*64 + mi*16 + grp;
                ar[mi][0] = *(const uint32_t*)&As[buf][r  ][k0  ];
                ar[mi][1] = *(const uint32_t*)&As[buf][r+8][k0  ];
                ar[mi][2] = *(const uint32_t*)&As[buf][r  ][k0+8];
                ar[mi][3] = *(const uint32_t*)&As[buf][r+8][k0+8];
            }
#pragma unroll
            for (int ni=0; ni<4; ni++){
                int n = wn*32 + ni*8 + grp;
                br[ni][0] = *(const uint32_t*)&Bs[buf][n][k0  ];
                br[ni][1] = *(const uint32_t*)&Bs[buf][n][k0+8];
            }
#pragma unroll
            for (int mi=0; mi<4; mi++)
#pragma unroll
                for (int ni=0; ni<4; ni++)
                    mma16816(acc[mi][ni], ar[mi], br[ni]);
        }
        __syncthreads();
    }
#undef GEMM_STAGE

#pragma unroll
    for (int mi=0; mi<4; mi++){
        size_t r = m0 + wm*64 + mi*16 + grp;
#pragma unroll
        for (int ni=0; ni<4; ni++){
            size_t n = n0 + wn*32 + ni*8 + tig*2;
            float b0 = bias[n], b1 = bias[n+1];
            Cout[ r   *NG + n  ] = acc[mi][ni][0] + b0;
            Cout[ r   *NG + n+1] = acc[mi][ni][1] + b1;
            Cout[(r+8)*NG + n  ] = acc[mi][ni][2] + b0;
            Cout[(r+8)*NG + n+1] = acc[mi][ni][3] + b1;
        }
    }
}

// ---------------- persistent recurrent scan ----------------
// 128 CTAs x 256 threads (8 warps). CTA owns hcols [cta*8, cta*8+8) across the
// 4 gates (N=32). Warp w owns k-slice [w*128, w*128+128):
//   - Wh fragments register-resident (loaded once from global)
//   - h[s-1] slice arrives via TMA (SW128, [k][b] rows of 128B) -> ldmatrix.x4.trans
//   - per-warp partial D[64x32] f32 -> smem reduction -> gate update
// Synchronization is dataflow, not a grid barrier: CTA c (k-group g=c>>4)
// signals cnt[g] after writing h[s]; consumer warp w of every CTA acquires
// cnt[w] >= 16*(s+1) before issuing its TMA for step s+1. The acquire spin
// backs off with __nanosleep to avoid saturating the LTS ld/atomic path
// (1024 spinner lanes on 8 lines; R5's hard spin is the suspected hang).
__global__ void __launch_bounds__(256,1) k_scan(int layer, float* __restrict__ out,
        const __grid_constant__ CUtensorMap mH)
{
    extern __shared__ __align__(1024) char dsm[];
    uint32_t raw  = (uint32_t)__cvta_generic_to_shared(dsm);
    uint32_t base = (raw + 1023u) & ~1023u;
    char* gb = dsm + (base - raw);
    uint32_t mb = base;                       // 8 mbarriers (8B each)
    uint32_t sA = base + 1024;                // 128KB: 8 slices x 16KB ([128k][128B])
    float* P  = (float*)(gb + 132096);        // 8 x [64][36] f32 partials (72KB)
    float* Cs = (float*)(gb + 205824);        // [64][36] f32 reduced

    const int tid  = threadIdx.x;
    const int lane = tid & 31, w = tid >> 5;
    const int grp  = lane >> 2, tig = lane & 3;
    const int hcol0 = blockIdx.x * 8;
    const int kgrp  = blockIdx.x >> 4;        // producer k-group of this CTA
    const __half* __restrict__ Whp = d_wth + (size_t)layer*NG*HID;
    __half* __restrict__ hsb = layer ? d_hs1 : d_hs0;

    if (tid < 8) MBARRIER_INIT(mb + tid*8, 1);

    // register-resident B fragments: brf[nt][kt][2]
    uint32_t brf[4][8][2];
#pragma unroll
    for (int nt = 0; nt < 4; nt++){
        const __half* rp = Whp + (size_t)(nt*1024 + hcol0 + grp)*1024 + w*128 + tig*2;
#pragma unroll
        for (int kt = 0; kt < 8; kt++){
            brf[nt][kt][0] = *(const uint32_t*)(rp + kt*16);
            brf[nt][kt][1] = *(const uint32_t*)(rp + kt*16 + 8);
        }
    }

    // ldmatrix lane constants (source [k][m], SW128 swizzle: col ^ ((k&7)<<4))
    const int q = lane >> 3, iq = lane & 7;
    const uint32_t rowoff = (uint32_t)((((q>>1)*8) + iq) * 128);
    const uint32_t cadd   = (uint32_t)((q & 1) * 16);
    const uint32_t ixor   = (uint32_t)(iq << 4);
    const uint32_t sAw    = sA + (uint32_t)w * 16384u;

    float creg0 = 0.f, creg1 = 0.f;
    const int b0r = tid >> 3, jj = tid & 7;
    const int b1r = 32 + b0r;
    const int hc  = hcol0 + jj;

    __syncthreads();

    for (int s = 0; s < SEQ; s++){
        const float* gxs = d_gx + (size_t)s*BATCH*NG;
        float p0i = gxs[(size_t)b0r*NG +        hc];
        float p0f = gxs[(size_t)b0r*NG + 1024 + hc];
        float p0g = gxs[(size_t)b0r*NG + 2048 + hc];
        float p0o = gxs[(size_t)b0r*NG + 3072 + hc];
        float p1i = gxs[(size_t)b1r*NG +        hc];
        float p1f = gxs[(size_t)b1r*NG + 1024 + hc];
        float p1g = gxs[(size_t)b1r*NG + 2048 + hc];
        float p1o = gxs[(size_t)b1r*NG + 3072 + hc];

        if (s > 0){
            MBARRIER_WAIT_PARITY(mb + w*8, (s-1)&1);
            float acc[4][4][4];
#pragma unroll
            for (int a=0;a<4;a++)
#pragma unroll
                for (int b=0;b<4;b++)
#pragma unroll
                    for (int c=0;c<4;c++) acc[a][b][c] = 0.f;

#pragma unroll
            for (int kt = 0; kt < 8; kt++){
                uint32_t rowk = sAw + (uint32_t)(kt*2048) + rowoff;
#pragma unroll
                for (int mt = 0; mt < 4; mt++){
                    uint32_t addr = rowk + (((uint32_t)(mt*32) + cadd) ^ ixor);
                    uint32_t a0,a1,a2,a3;
                    LDSM_X4_T(a0,a1,a2,a3, addr);
                    uint32_t ar[4] = {a0,a1,a2,a3};
#pragma unroll
                    for (int nt = 0; nt < 4; nt++)
                        mma16816(acc[mt][nt], ar, brf[nt][kt]);
                }
            }
            // partial store: P[w][m][n], row stride 36 floats
            float* Pw = P + w*2304;
#pragma unroll
            for (int mt = 0; mt < 4; mt++){
                int m = mt*16 + grp;
#pragma unroll
                for (int nt = 0; nt < 4; nt++){
                    int n = nt*8 + tig*2;
                    *(float2*)(Pw + (size_t)m*36 + n)     = make_float2(acc[mt][nt][0], acc[mt][nt][1]);
                    *(float2*)(Pw + (size_t)(m+8)*36 + n) = make_float2(acc[mt][nt][2], acc[mt][nt][3]);
                }
            }
        }
        __syncthreads();

        if (s > 0){
            // cross-warp reduce: thread t owns row m=t>>2, cols (t&3)*8..+8
            int m = tid >> 2, nb = (tid & 3)*8;
            float r0=0,r1=0,r2=0,r3=0,r4=0,r5=0,r6=0,r7=0;
#pragma unroll
            for (int ww = 0; ww < 8; ww++){
                const float4* pp = (const float4*)(P + ww*2304 + m*36 + nb);
                float4 x = pp[0], y = pp[1];
                r0+=x.x; r1+=x.y; r2+=x.z; r3+=x.w;
                r4+=y.x; r5+=y.y; r6+=y.z; r7+=y.w;
            }
            *(float4*)(Cs + m*36 + nb)     = make_float4(r0,r1,r2,r3);
            *(float4*)(Cs + m*36 + nb + 4) = make_float4(r4,r5,r6,r7);
        } else {
            for (int i = tid; i < 2304; i += 256) Cs[i] = 0.f;
        }
        __syncthreads();

        // gate + state update (thread handles (b0r, jj) and (b1r, jj))
        {
            float xi = Cs[b0r*36 +      jj] + p0i;
            float xf = Cs[b0r*36 +  8 + jj] + p0f;
            float xg = Cs[b0r*36 + 16 + jj] + p0g;
            float xo = Cs[b0r*36 + 24 + jj] + p0o;
            float iv = 1.f/(1.f + expf(-xi));
            float fv = 1.f/(1.f + expf(-xf));
            float gv = tanhf(xg);
            float ov = 1.f/(1.f + expf(-xo));
            float cn = fv*creg0 + iv*gv;
            creg0 = cn;
            float hv = ov * tanhf(cn);
            hsb[(size_t)s*65536 + (size_t)hc*64 + b0r] = __float2half(hv);
            if (s == SEQ-1){
                size_t o1 = (size_t)b0r*HID + hc;
                out[ 65536 + (size_t)layer*65536 + o1] = hv;
                out[196608 + (size_t)layer*65536 + o1] = cn;
                if (layer == 1) out[o1] = hv;
            }
        }
        {
            float xi = Cs[b1r*36 +      jj] + p1i;
            float xf = Cs[b1r*36 +  8 + jj] + p1f;
            float xg = Cs[b1r*36 + 16 + jj] + p1g;
            float xo = Cs[b1r*36 + 24 + jj] + p1o;
            float iv = 1.f/(1.f + expf(-xi));
            float fv = 1.f/(1.f + expf(-xf));
            float gv = tanhf(xg);
            float ov = 1.f/(1.f + expf(-xo));
            float cn = fv*creg1 + iv*gv;
            creg1 = cn;
            float hv = ov * tanhf(cn);
            hsb[(size_t)s*65536 + (size_t)hc*64 + b1r] = __float2half(hv);
            if (s == SEQ-1){
                size_t o1 = (size_t)b1r*HID + hc;
                out[ 65536 + (size_t)layer*65536 + o1] = hv;
                out[196608 + (size_t)layer*65536 + o1] = cn;
                if (layer == 1) out[o1] = hv;
            }
        }

        // producer signal: h[s] of this CTA fully stored -> bump group counter
        __syncthreads();
        if (tid == 0) red_release_add(&d_cnt[kgrp*32]);

        // consumer: wait for all 16 producers of k-group w, then pull h[s]
        if (s < SEQ-1){
            if (lane == 0){
                unsigned tgt = 16u*(unsigned)(s+1);
                if (ld_acquire(&d_cnt[w*32]) < tgt){
                    unsigned slp = 20u;
                    while (ld_acquire(&d_cnt[w*32]) < tgt){
                        __nanosleep(slp);
                        if (slp < 200u) slp += 60u;
                    }
                }
                MBARRIER_EXPECT_TX(mb + w*8, 16384);
                TMA_LOAD_3D(sAw, &mH, 0, w*128, s, mb + w*8);
            }
        }
    }
}

// ---------------- host: tensormap encode + launch ----------------
typedef CUresult (*PFN_encTiled)(CUtensorMap*, CUtensorMapDataType, cuuint32_t, void*,
                                 const cuuint64_t*, const cuuint64_t*, const cuuint32_t*,
                                 const cuuint32_t*, CUtensorMapInterleave, CUtensorMapSwizzle,
                                 CUtensorMapL2promotion, CUtensorMapFloatOOBfill);

static void enc_map_h(CUtensorMap* m, void* g){
    static PFN_encTiled fn = nullptr;
    if (!fn){
        cudaDriverEntryPointQueryResult qr;
        cudaGetDriverEntryPointByVersion("cuTensorMapEncodeTiled", (void**)&fn,
                                         12000, cudaEnableDefault, &qr);
    }
    cuuint64_t dims[3] = { 64, 1024, 512 };           // (b, k, s)
    cuuint64_t st[2]   = { 128ull, 131072ull };       // k stride 128B, s stride 128KB
    cuuint32_t box[3]  = { 64, 128, 1 };              // one warp k-slice
    cuuint32_t es[3]   = { 1, 1, 1 };
    fn(m, CU_TENSOR_MAP_DATA_TYPE_FLOAT16, 3, g, dims, st, box, es,
       CU_TENSOR_MAP_INTERLEAVE_NONE, CU_TENSOR_MAP_SWIZZLE_128B,
       CU_TENSOR_MAP_L2_PROMOTION_L2_128B, CU_TENSOR_MAP_FLOAT_OOB_FILL_NONE);
}

extern "C" void kernel_launch(void* const* d_in, const int* in_sizes, int n_in,
                              void* d_out, int out_size){
    const float* x  = (const float*)d_in[0];
    const float* Wi = (const float*)d_in[1];
    const float* bi = (const float*)d_in[2];
    const float* Wh = (const float*)d_in[3];
    const float* bh = (const float*)d_in[4];
    float* out = (float*)d_out;

    void *p_hs0, *p_hs1;
    cudaGetSymbolAddress(&p_hs0, d_hs0);
    cudaGetSymbolAddress(&p_hs1, d_hs1);

    CUtensorMap mH0, mH1;
    enc_map_h(&mH0, p_hs0);
    enc_map_h(&mH1, p_hs1);

    const int SCAN_SMEM = 1024 + 131072 + 73728 + 9216 + 1024;  // 216,064 B
    cudaFuncSetAttribute(k_scan, cudaFuncAttributeMaxDynamicSharedMemorySize, SCAN_SMEM);

    k_convx<<<(MROWS*HID)/256, 256>>>(x);
    k_convw<<<dim3(32,32,16), dim3(32,32)>>>(Wi, Wh);
    k_bias<<<32, 256>>>(bi, bh);

    k_gemm<<<dim3(NG/128, MROWS/128), 256>>>(0);
    k_zc<<<1, 256>>>();
    k_scan<<<128, 256, SCAN_SMEM>>>(0, out, mH0);
    k_trans<<<dim3(512, 32), dim3(32, 32)>>>();
    k_gemm<<<dim3(NG/128, MROWS/128), 256>>>(1);
    k_zc<<<1, 256>>>();
    k_scan<<<128, 256, SCAN_SMEM>>>(1, out, mH1);
}